// round 1
// baseline (speedup 1.0000x reference)
#include <cuda_runtime.h>

#define D_DIM 256
#define K_DIM 512
#define BM 128
#define BN 128
#define BK 16

// 0 = int32 mask, 1 = uint8 mask, 2 = float32 mask
__device__ int   g_mask_kind;
__device__ float g_esq[K_DIM];
__device__ float g_partials[1024];

static __device__ __forceinline__ unsigned long long dup_f32x2(float x) {
    unsigned long long r;
    unsigned int u = __float_as_uint(x);
    asm("mov.b64 %0, {%1, %1};" : "=l"(r) : "r"(u));
    return r;
}

// ---------------------------------------------------------------------------
// prep: detect mask dtype + compute ||e_k||^2
// ---------------------------------------------------------------------------
__global__ void prep_kernel(const float* __restrict__ cb,
                            const void* __restrict__ mask,
                            int mask_words) {
    __shared__ int s_int_ok, s_float_ok;
    int tid = threadIdx.x;
    if (tid == 0) { s_int_ok = 1; s_float_ok = 1; }
    __syncthreads();
    if (tid < 256) {
        const unsigned int* mw = (const unsigned int*)mask;
        int iok = 1, fok = 1;
        for (int j = 0; j < 4; j++) {
            int w = tid * 4 + j;
            if (w < mask_words) {
                unsigned int v = mw[w];
                if (v > 1u) iok = 0;
                if (v != 0u && v != 0x3F800000u) fok = 0;
            }
        }
        if (!iok) atomicAnd(&s_int_ok, 0);
        if (!fok) atomicAnd(&s_float_ok, 0);
    }
    if (tid < K_DIM) {
        const float4* row = (const float4*)(cb + (long long)tid * D_DIM);
        float s = 0.f;
        #pragma unroll 8
        for (int i = 0; i < D_DIM / 4; i++) {
            float4 v = row[i];
            s += v.x * v.x + v.y * v.y + v.z * v.z + v.w * v.w;
        }
        g_esq[tid] = s;
    }
    __syncthreads();
    if (tid == 0) g_mask_kind = s_int_ok ? 0 : (s_float_ok ? 2 : 1);
}

// ---------------------------------------------------------------------------
// main: distances (f32x2-packed GEMM), argmin, gather, mask, loss partials
// ---------------------------------------------------------------------------
__global__ __launch_bounds__(256, 2)
void vq_kernel(const float* __restrict__ z,
               const void* __restrict__ mask,
               const float* __restrict__ cb,
               float* __restrict__ out,
               int T, int write_idx, int write_loss) {
    __shared__ __align__(16) float As[BK][132];   // [d][token], padded pitch
    __shared__ __align__(16) float Bs[BK][BN];    // [d][k]
    __shared__ int   s_idx[BM];
    __shared__ float s_red[256];

    const int tid = threadIdx.x;
    const int tx = tid & 15;       // k-direction (8 codes each)
    const int ty = tid >> 4;       // token-direction (8 tokens each)
    const long long tbase = (long long)blockIdx.x * BM;

    float bestv[8];
    int   besti[8];
    #pragma unroll
    for (int i = 0; i < 8; i++) { bestv[i] = 3.4e38f; besti[i] = 0; }

    for (int kc = 0; kc < K_DIM / BN; kc++) {
        unsigned long long acc[8][4];
        #pragma unroll
        for (int i = 0; i < 8; i++)
            #pragma unroll
            for (int p = 0; p < 4; p++) acc[i][p] = 0ull;  // (0.0f, 0.0f)

        for (int dc = 0; dc < D_DIM / BK; dc++) {
            // cooperative load (transposed into [d][x] layout)
            #pragma unroll
            for (int r = 0; r < 2; r++) {
                int i   = tid + 256 * r;
                int row = i >> 2;
                int q   = i & 3;
                float4 v = *(const float4*)(z  + (tbase + row) * D_DIM + dc * BK + q * 4);
                As[q * 4 + 0][row] = v.x; As[q * 4 + 1][row] = v.y;
                As[q * 4 + 2][row] = v.z; As[q * 4 + 3][row] = v.w;
                float4 w = *(const float4*)(cb + (long long)(kc * BN + row) * D_DIM + dc * BK + q * 4);
                Bs[q * 4 + 0][row] = w.x; Bs[q * 4 + 1][row] = w.y;
                Bs[q * 4 + 2][row] = w.z; Bs[q * 4 + 3][row] = w.w;
            }
            __syncthreads();

            const float4*     As4 = (const float4*)As;       // row pitch = 33 float4
            const ulonglong2* Bs2 = (const ulonglong2*)Bs;   // row pitch = 32 ull2
            #pragma unroll
            for (int d = 0; d < BK; d++) {
                float4 A0 = As4[d * 33 + ty * 2];
                float4 A1 = As4[d * 33 + ty * 2 + 1];
                unsigned long long a[8];
                a[0] = dup_f32x2(A0.x); a[1] = dup_f32x2(A0.y);
                a[2] = dup_f32x2(A0.z); a[3] = dup_f32x2(A0.w);
                a[4] = dup_f32x2(A1.x); a[5] = dup_f32x2(A1.y);
                a[6] = dup_f32x2(A1.z); a[7] = dup_f32x2(A1.w);
                ulonglong2 b01 = Bs2[d * 32 + tx * 2];
                ulonglong2 b23 = Bs2[d * 32 + tx * 2 + 1];
                unsigned long long b[4] = { b01.x, b01.y, b23.x, b23.y };
                #pragma unroll
                for (int i = 0; i < 8; i++)
                    #pragma unroll
                    for (int p = 0; p < 4; p++)
                        asm("fma.rn.f32x2 %0, %1, %2, %0;"
                            : "+l"(acc[i][p]) : "l"(a[i]), "l"(b[p]));
            }
            __syncthreads();
        }

        // scores + running argmin (tie-break: lowest k, like jnp.argmin)
        float eq[8];
        #pragma unroll
        for (int j = 0; j < 8; j++) eq[j] = g_esq[kc * BN + tx * 8 + j];
        #pragma unroll
        for (int i = 0; i < 8; i++) {
            float v = 3.4e38f; int vi = 0;
            #pragma unroll
            for (int p = 0; p < 4; p++) {
                unsigned int lo, hi;
                asm("mov.b64 {%0, %1}, %2;" : "=r"(lo), "=r"(hi) : "l"(acc[i][p]));
                float s0 = eq[2 * p]     - 2.0f * __uint_as_float(lo);
                float s1 = eq[2 * p + 1] - 2.0f * __uint_as_float(hi);
                int k0 = kc * BN + tx * 8 + 2 * p;
                if (s0 < v) { v = s0; vi = k0; }
                if (s1 < v) { v = s1; vi = k0 + 1; }
            }
            #pragma unroll
            for (int m = 8; m >= 1; m >>= 1) {
                float ov = __shfl_xor_sync(0xFFFFFFFFu, v,  m);
                int   oi = __shfl_xor_sync(0xFFFFFFFFu, vi, m);
                if (ov < v || (ov == v && oi < vi)) { v = ov; vi = oi; }
            }
            if (v < bestv[i]) { bestv[i] = v; besti[i] = vi; }
        }
    }

    if (tx == 0) {
        #pragma unroll
        for (int i = 0; i < 8; i++) s_idx[ty * 8 + i] = besti[i];
    }
    __syncthreads();

    // epilogue: gather codeword, straight-through quantize, mask, loss
    const int mkind = g_mask_kind;
    const unsigned char* m8  = (const unsigned char*)mask;
    const int*           m32 = (const int*)mask;
    const float*         mf  = (const float*)mask;

    float lsum = 0.f;
    const int d = tid;  // blockDim == D_DIM
    for (int t = 0; t < BM; t++) {
        long long gt = tbase + t;
        int k = s_idx[t];
        float mval;
        if (mkind == 0)      mval = m32[gt] ? 1.f : 0.f;
        else if (mkind == 1) mval = m8[gt]  ? 1.f : 0.f;
        else                 mval = mf[gt];
        float e  = cb[(long long)k * D_DIM + d];
        float zz = z[gt * D_DIM + d];
        float t1 = e - zz;
        float q  = zz + t1;          // straight-through forward (matches ref rounding)
        float df = q - zz;
        lsum += df * df;             // loss is pre-mask in the reference
        out[gt * D_DIM + d] = q * mval;
    }

    if (write_idx && tid < BM) {
        long long gt = tbase + tid;
        int k = s_idx[tid];
        bool on;
        if (mkind == 0)      on = (m32[gt] != 0);
        else if (mkind == 1) on = (m8[gt] != 0);
        else                 on = (mf[gt] != 0.f);
        out[(long long)T * D_DIM + gt] = on ? (float)k : -1.0f;
    }

    if (write_loss) {
        s_red[tid] = lsum;
        __syncthreads();
        for (int s = 128; s > 0; s >>= 1) {
            if (tid < s) s_red[tid] += s_red[tid + s];
            __syncthreads();
        }
        if (tid == 0) g_partials[blockIdx.x] = s_red[0];
    }
}

// ---------------------------------------------------------------------------
// final deterministic loss reduction
// ---------------------------------------------------------------------------
__global__ void loss_kernel(float* __restrict__ out, long long loss_off,
                            int nblocks, float inv_bnd) {
    __shared__ float s[256];
    int tid = threadIdx.x;
    float v = 0.f;
    for (int i = tid; i < nblocks; i += 256) v += g_partials[i];
    s[tid] = v;
    __syncthreads();
    for (int st = 128; st > 0; st >>= 1) {
        if (tid < st) s[tid] += s[tid + st];
        __syncthreads();
    }
    if (tid == 0) out[loss_off] = 0.25f * s[0] * inv_bnd;
}

// ---------------------------------------------------------------------------
extern "C" void kernel_launch(void* const* d_in, const int* in_sizes, int n_in,
                              void* d_out, int out_size) {
    const float* z    = (const float*)d_in[0];
    const void*  mask = d_in[1];
    const float* cb   = (const float*)d_in[2];
    float* out = (float*)d_out;

    long long BND = in_sizes[0];         // B*N*D = 16777216
    int T = in_sizes[1];                 // B*N   = 65536

    int mask_words = (T / 4 < 1024) ? (T / 4) : 1024;  // safe for all dtype guesses
    prep_kernel<<<1, 512>>>(cb, mask, mask_words);

    int nb = T / BM;                     // 512 blocks
    int write_idx  = ((long long)out_size >= BND + T) ? 1 : 0;
    int write_loss = ((long long)out_size >= BND + T + 1) ? 1 : 0;

    vq_kernel<<<nb, 256>>>(z, mask, cb, out, T, write_idx, write_loss);

    if (write_loss)
        loss_kernel<<<1, 256>>>(out, BND + T, nb, 1.0f / (float)BND);
}

// round 3
// speedup vs baseline: 1.8881x; 1.8881x over previous
#include <cuda_runtime.h>
#include <cuda_bf16.h>
#include <cstdint>

#define D_DIM   256
#define K_DIM   512
#define TILE_M  128
#define NTILES  512
#define THRESH  0.02f

// ---------------- device globals (no runtime allocs) ------------------------
__device__ __align__(16) unsigned short g_cbH[K_DIM * D_DIM];  // bf16 hi split
__device__ __align__(16) unsigned short g_cbL[K_DIM * D_DIM];  // bf16 lo split
__device__ float g_esq[K_DIM];
__device__ float g_partials[NTILES];
__device__ int   g_mask_kind;   // 0=int32, 1=uint8, 2=float32

// ---------------- smem layout (dynamic) -------------------------------------
#define OFF_AH    0           // z hi: 128 rows x 512B (swizzled)
#define OFF_AL    65536       // z lo
#define OFF_B     131072      // 2 bufs x (H 16KB + L 16KB)
#define OFF_ESQ   196608      // 512 f
#define OFF_V1    198656      // 128 f
#define OFF_V2    199168
#define OFF_I1    199680      // 128 i
#define OFF_ZSQ   200704      // 128 f
#define OFF_MV    201216      // 128 f
#define OFF_NFL   201728
#define OFF_FLIST 201744      // 128 i
#define OFF_RV    202368      // 256 f
#define OFF_RI    203392      // 256 i
#define OFF_ZROW  204416      // 256 f
#define SMEM_TOTAL 205824

// ---------------- helpers ---------------------------------------------------
static __device__ __forceinline__ uint32_t smem_u32(const void* p) {
    uint32_t a;
    asm("{ .reg .u64 t; cvta.to.shared.u64 t, %1; cvt.u32.u64 %0, t; }" : "=r"(a) : "l"(p));
    return a;
}
#define LDSM_X4(r0,r1,r2,r3,addr) \
    asm volatile("ldmatrix.sync.aligned.m8n8.x4.shared.b16 {%0,%1,%2,%3}, [%4];" \
        : "=r"(r0),"=r"(r1),"=r"(r2),"=r"(r3) : "r"(addr))
#define MMA_BF16(dd, a0,a1,a2,a3, b0,b1) \
    asm volatile("mma.sync.aligned.m16n8k16.row.col.f32.bf16.bf16.f32 " \
        "{%0,%1,%2,%3}, {%4,%5,%6,%7}, {%8,%9}, {%0,%1,%2,%3};" \
        : "+f"((dd)[0]),"+f"((dd)[1]),"+f"((dd)[2]),"+f"((dd)[3]) \
        : "r"(a0),"r"(a1),"r"(a2),"r"(a3),"r"(b0),"r"(b1))
#define CP_ASYNC16(dst, src) \
    asm volatile("cp.async.cg.shared.global [%0], [%1], 16;" :: "r"(dst), "l"(src) : "memory")
#define CP_COMMIT() asm volatile("cp.async.commit_group;" ::: "memory")
#define CP_WAIT1()  asm volatile("cp.async.wait_group 1;" ::: "memory")
#define CP_WAIT0()  asm volatile("cp.async.wait_group 0;" ::: "memory")

static __device__ __forceinline__ void splitf(float v, unsigned short& hb, unsigned short& lb) {
    __nv_bfloat16 h = __float2bfloat16_rn(v);
    hb = *reinterpret_cast<unsigned short*>(&h);
    float hf = __bfloat162float(h);
    __nv_bfloat16 l = __float2bfloat16_rn(v - hf);
    lb = *reinterpret_cast<unsigned short*>(&l);
}

// ---------------- prep: mask dtype + ||e||^2 --------------------------------
__global__ void prep_kernel(const float* __restrict__ cb,
                            const void* __restrict__ mask, int mask_words) {
    __shared__ int s_int_ok, s_float_ok;
    int tid = threadIdx.x;
    if (tid == 0) { s_int_ok = 1; s_float_ok = 1; }
    __syncthreads();
    if (tid < 256) {
        const unsigned int* mw = (const unsigned int*)mask;
        int iok = 1, fok = 1;
        for (int j = 0; j < 4; j++) {
            int w = tid * 4 + j;
            if (w < mask_words) {
                unsigned int v = mw[w];
                if (v > 1u) iok = 0;
                if (v != 0u && v != 0x3F800000u) fok = 0;
            }
        }
        if (!iok) atomicAnd(&s_int_ok, 0);
        if (!fok) atomicAnd(&s_float_ok, 0);
    }
    if (tid < K_DIM) {
        const float4* row = (const float4*)(cb + (size_t)tid * D_DIM);
        float s = 0.f;
        #pragma unroll 8
        for (int i = 0; i < D_DIM / 4; i++) {
            float4 v = row[i];
            s += v.x * v.x + v.y * v.y + v.z * v.z + v.w * v.w;
        }
        g_esq[tid] = s;
    }
    __syncthreads();
    if (tid == 0) g_mask_kind = s_int_ok ? 0 : (s_float_ok ? 2 : 1);
}

// ---------------- codebook -> bf16 split arrays (plain row-major) -----------
__global__ void convert_cb_kernel(const float* __restrict__ cb) {
    int gid = blockIdx.x * blockDim.x + threadIdx.x;   // 32768 threads
    int k = gid >> 6;
    int dq = (gid & 63) * 4;
    float4 v = *(const float4*)(cb + (size_t)k * D_DIM + dq);
    unsigned short hb[4], lb[4];
    splitf(v.x, hb[0], lb[0]); splitf(v.y, hb[1], lb[1]);
    splitf(v.z, hb[2], lb[2]); splitf(v.w, hb[3], lb[3]);
    uint2 H, L;
    H.x = (uint32_t)hb[0] | ((uint32_t)hb[1] << 16);
    H.y = (uint32_t)hb[2] | ((uint32_t)hb[3] << 16);
    L.x = (uint32_t)lb[0] | ((uint32_t)lb[1] << 16);
    L.y = (uint32_t)lb[2] | ((uint32_t)lb[3] << 16);
    *(uint2*)(g_cbH + (size_t)k * D_DIM + dq) = H;
    *(uint2*)(g_cbL + (size_t)k * D_DIM + dq) = L;
}

// ---------------- B chunk prefetch (cp.async, swizzled dst) -----------------
static __device__ __forceinline__ void prefetch_B(char* smem, int buf, int nc, int kc, int tid) {
    uint32_t dst_base = smem_u32(smem + OFF_B + buf * 32768);
    #pragma unroll
    for (int j = 0; j < 8; j++) {
        int id = tid + 256 * j;        // 2048 granules: [split][n 128][g 8]
        int s   = id >> 10;
        int rem = id & 1023;
        int n   = rem >> 3;
        int g   = rem & 7;
        const unsigned char* src =
            (const unsigned char*)(s ? g_cbL : g_cbH)
            + (size_t)(nc * 128 + n) * 512 + kc * 128 + g * 16;
        uint32_t dst = dst_base + s * 16384 + n * 128 + ((g ^ (n & 7)) << 4);
        CP_ASYNC16(dst, src);
    }
    CP_COMMIT();
}

// ---------------- main fused kernel -----------------------------------------
__global__ __launch_bounds__(256, 1)
void vq_mma_kernel(const float* __restrict__ z,
                   const void* __restrict__ mask,
                   const float* __restrict__ cb,
                   float* __restrict__ out,
                   int T, int write_idx, int write_loss) {
    extern __shared__ __align__(1024) char smem[];
    const uint32_t sb = smem_u32(smem);
    const int tid = threadIdx.x, w = tid >> 5, lane = tid & 31;
    const long long tbase = (long long)blockIdx.x * TILE_M;

    float* s_esq = (float*)(smem + OFF_ESQ);
    float* s_v1  = (float*)(smem + OFF_V1);
    float* s_v2  = (float*)(smem + OFF_V2);
    int*   s_i1  = (int*)  (smem + OFF_I1);
    float* s_zsq = (float*)(smem + OFF_ZSQ);
    float* s_mv  = (float*)(smem + OFF_MV);
    int*   s_nfl = (int*)  (smem + OFF_NFL);
    int*   s_fls = (int*)  (smem + OFF_FLIST);
    float* s_rv  = (float*)(smem + OFF_RV);
    int*   s_ri  = (int*)  (smem + OFF_RI);
    float* s_zrow= (float*)(smem + OFF_ZROW);

    if (tid == 0) *s_nfl = 0;

    // kick first B chunk while we convert A
    prefetch_B(smem, 0, 0, 0, tid);

    // stage esq
    s_esq[tid] = g_esq[tid];
    s_esq[256 + tid] = g_esq[256 + tid];

    // ---- convert z tile -> swizzled bf16 H/L smem; accumulate z_sq ----
    {
        const int r = tid >> 1, h = tid & 1;
        const float4* zr = (const float4*)(z + (tbase + r) * D_DIM);
        float zs = 0.f;
        #pragma unroll 4
        for (int j = 0; j < 16; j++) {
            int k0 = h * 128 + j * 8;
            float4 q0 = zr[k0 / 4], q1 = zr[k0 / 4 + 1];
            float vs[8] = { q0.x, q0.y, q0.z, q0.w, q1.x, q1.y, q1.z, q1.w };
            unsigned short hb[8], lb[8];
            #pragma unroll
            for (int e = 0; e < 8; e++) { splitf(vs[e], hb[e], lb[e]); zs += vs[e] * vs[e]; }
            uint4 H, L;
            H.x = (uint32_t)hb[0] | ((uint32_t)hb[1] << 16);
            H.y = (uint32_t)hb[2] | ((uint32_t)hb[3] << 16);
            H.z = (uint32_t)hb[4] | ((uint32_t)hb[5] << 16);
            H.w = (uint32_t)hb[6] | ((uint32_t)hb[7] << 16);
            L.x = (uint32_t)lb[0] | ((uint32_t)lb[1] << 16);
            L.y = (uint32_t)lb[2] | ((uint32_t)lb[3] << 16);
            L.z = (uint32_t)lb[4] | ((uint32_t)lb[5] << 16);
            L.w = (uint32_t)lb[6] | ((uint32_t)lb[7] << 16);
            int g  = h * 16 + j;
            int gp = g ^ (r & 7);
            *(uint4*)(smem + OFF_AH + r * 512 + gp * 16) = H;
            *(uint4*)(smem + OFF_AL + r * 512 + gp * 16) = L;
        }
        s_rv[tid] = zs;   // pair-reduce below
    }
    __syncthreads();
    if (tid < TILE_M) s_zsq[tid] = s_rv[2 * tid] + s_rv[2 * tid + 1];

    // ---- GEMM + in-register argmin ----
    float vA1 = 3.0e38f, vA2 = 3.0e38f, vB1 = 3.0e38f, vB2 = 3.0e38f;
    int iA1 = 0, iB1 = 0;
    const int rA = w * 16 + (lane >> 2);                 // lane's row (c0/c1)
    const int arow = w * 16 + (lane & 15);               // ldmatrix A row
    const uint32_t aBaseH = sb + OFF_AH + arow * 512;
    const uint32_t aBaseL = sb + OFF_AL + arow * 512;
    const int aXor = arow & 7, aQ = lane >> 4;
    const int bn = (lane & 7) + ((lane >= 16) ? 8 : 0);  // ldmatrix B row (within n16)
    const int bQ = (lane >> 3) & 1;

    for (int nc = 0; nc < 4; nc++) {
        float d[16][4];
        #pragma unroll
        for (int t = 0; t < 16; t++)
            #pragma unroll
            for (int q = 0; q < 4; q++) d[t][q] = 0.f;

        for (int kc = 0; kc < 4; kc++) {
            int ci = nc * 4 + kc;
            if (ci < 15) {
                int cn = ci + 1;
                prefetch_B(smem, cn & 1, cn >> 2, cn & 3, tid);
                CP_WAIT1();
            } else {
                CP_WAIT0();
            }
            __syncthreads();
            const uint32_t bBuf = sb + OFF_B + (ci & 1) * 32768;

            for (int ks = 0; ks < 4; ks++) {
                int gA = ((kc * 8 + ks * 2 + aQ) ^ aXor) << 4;
                uint32_t ah0, ah1, ah2, ah3, al0, al1, al2, al3;
                LDSM_X4(ah0, ah1, ah2, ah3, aBaseH + gA);
                LDSM_X4(al0, al1, al2, al3, aBaseL + gA);
                #pragma unroll
                for (int np = 0; np < 8; np++) {
                    int n = np * 16 + bn;
                    uint32_t baddr = bBuf + n * 128 + (((ks * 2 + bQ) ^ (n & 7)) << 4);
                    uint32_t bh0, bh1, bh2, bh3, bl0, bl1, bl2, bl3;
                    LDSM_X4(bh0, bh1, bh2, bh3, baddr);
                    LDSM_X4(bl0, bl1, bl2, bl3, baddr + 16384);
                    MMA_BF16(d[2*np],   ah0, ah1, ah2, ah3, bh0, bh1);
                    MMA_BF16(d[2*np+1], ah0, ah1, ah2, ah3, bh2, bh3);
                    MMA_BF16(d[2*np],   al0, al1, al2, al3, bh0, bh1);
                    MMA_BF16(d[2*np+1], al0, al1, al2, al3, bh2, bh3);
                    MMA_BF16(d[2*np],   ah0, ah1, ah2, ah3, bl0, bl1);
                    MMA_BF16(d[2*np+1], ah0, ah1, ah2, ah3, bl2, bl3);
                }
            }
            __syncthreads();
        }

        // fold this n-chunk into running argmin (ascending k => lowest-index ties)
        #pragma unroll
        for (int t = 0; t < 16; t++) {
            int c0 = nc * 128 + t * 8 + 2 * (lane & 3);
            float e0 = s_esq[c0], e1 = s_esq[c0 + 1];
            float s0 = fmaf(-2.f, d[t][0], e0);
            float s1 = fmaf(-2.f, d[t][1], e1);
            float s2 = fmaf(-2.f, d[t][2], e0);
            float s3 = fmaf(-2.f, d[t][3], e1);
            if (s0 < vA1) { vA2 = vA1; vA1 = s0; iA1 = c0; }     else if (s0 < vA2) vA2 = s0;
            if (s1 < vA1) { vA2 = vA1; vA1 = s1; iA1 = c0 + 1; } else if (s1 < vA2) vA2 = s1;
            if (s2 < vB1) { vB2 = vB1; vB1 = s2; iB1 = c0; }     else if (s2 < vB2) vB2 = s2;
            if (s3 < vB1) { vB2 = vB1; vB1 = s3; iB1 = c0 + 1; } else if (s3 < vB2) vB2 = s3;
        }
    }

    // quad reduce (lanes sharing a row)
    #pragma unroll
    for (int m = 1; m <= 2; m <<= 1) {
        float o1 = __shfl_xor_sync(0xFFFFFFFFu, vA1, m);
        int   oi = __shfl_xor_sync(0xFFFFFFFFu, iA1, m);
        float o2 = __shfl_xor_sync(0xFFFFFFFFu, vA2, m);
        float n2 = fminf(fmaxf(vA1, o1), fminf(vA2, o2));
        if (o1 < vA1 || (o1 == vA1 && oi < iA1)) { vA1 = o1; iA1 = oi; }
        vA2 = n2;
        float p1 = __shfl_xor_sync(0xFFFFFFFFu, vB1, m);
        int   pi = __shfl_xor_sync(0xFFFFFFFFu, iB1, m);
        float p2 = __shfl_xor_sync(0xFFFFFFFFu, vB2, m);
        float q2 = fminf(fmaxf(vB1, p1), fminf(vB2, p2));
        if (p1 < vB1 || (p1 == vB1 && pi < iB1)) { vB1 = p1; iB1 = pi; }
        vB2 = q2;
    }
    if ((lane & 3) == 0) {
        s_v1[rA] = vA1; s_v2[rA] = vA2; s_i1[rA] = iA1;
        s_v1[rA + 8] = vB1; s_v2[rA + 8] = vB2; s_i1[rA + 8] = iB1;
    }
    __syncthreads();
    if (tid < TILE_M) {
        if (s_v2[tid] - s_v1[tid] < THRESH) {
            int p = atomicAdd(s_nfl, 1);
            if (p < 128) s_fls[p] = tid;
        }
    }
    __syncthreads();

    // ---- exact fp32 fallback for ambiguous tokens (rare) ----
    int nf = *s_nfl; if (nf > 128) nf = 128;
    for (int f = 0; f < nf; f++) {
        const int t = s_fls[f];
        s_zrow[tid] = z[(tbase + t) * D_DIM + tid];
        __syncthreads();
        float best = 3.0e38f; int bi = 0;
        #pragma unroll 1
        for (int rep = 0; rep < 2; rep++) {
            int k = tid + rep * 256;
            const float4* crow = (const float4*)(cb + (size_t)k * D_DIM);
            const float4* zr4 = (const float4*)s_zrow;
            float acc = 0.f;
            #pragma unroll 8
            for (int q = 0; q < 64; q++) {
                float4 a = zr4[q]; float4 b = crow[q];
                acc += a.x * b.x + a.y * b.y + a.z * b.z + a.w * b.w;
            }
            float sc = s_esq[k] - 2.0f * acc;
            if (sc < best) { best = sc; bi = k; }
        }
        s_rv[tid] = best; s_ri[tid] = bi;
        __syncthreads();
        for (int st = 128; st > 0; st >>= 1) {
            if (tid < st) {
                float ov = s_rv[tid + st]; int oi2 = s_ri[tid + st];
                if (ov < s_rv[tid] || (ov == s_rv[tid] && oi2 < s_ri[tid])) {
                    s_rv[tid] = ov; s_ri[tid] = oi2;
                }
            }
            __syncthreads();
        }
        if (tid == 0) { s_i1[t] = s_ri[0]; s_v1[t] = s_rv[0]; }
        __syncthreads();
    }

    // ---- epilogue: mask, indices, quantized, loss ----
    const int mkind = g_mask_kind;
    if (tid < TILE_M) {
        long long gt = tbase + tid;
        float mval;
        if (mkind == 0)      mval = ((const int*)mask)[gt] ? 1.f : 0.f;
        else if (mkind == 1) mval = ((const unsigned char*)mask)[gt] ? 1.f : 0.f;
        else                 mval = ((const float*)mask)[gt];
        s_mv[tid] = mval;
        if (write_idx)
            out[(long long)T * D_DIM + gt] = (mval != 0.f) ? (float)s_i1[tid] : -1.0f;
    }
    __syncthreads();
    {
        const int dcol = tid;
        #pragma unroll 4
        for (int t = 0; t < TILE_M; t++) {
            int k = s_i1[t];
            out[(tbase + t) * D_DIM + dcol] = cb[(size_t)k * D_DIM + dcol] * s_mv[t];
        }
    }
    if (write_loss) {
        if (tid < TILE_M) s_rv[tid] = s_zsq[tid] + s_v1[tid];   // ||z-e||^2
        __syncthreads();
        for (int st = 64; st > 0; st >>= 1) {
            if (tid < st) s_rv[tid] += s_rv[tid + st];
            __syncthreads();
        }
        if (tid == 0) g_partials[blockIdx.x] = s_rv[0];
    }
}

// ---------------- final deterministic loss reduction ------------------------
__global__ void loss_kernel(float* __restrict__ out, long long loss_off,
                            int nblocks, float inv_bnd) {
    __shared__ float s[256];
    int tid = threadIdx.x;
    float v = 0.f;
    for (int i = tid; i < nblocks; i += 256) v += g_partials[i];
    s[tid] = v;
    __syncthreads();
    for (int st = 128; st > 0; st >>= 1) {
        if (tid < st) s[tid] += s[tid + st];
        __syncthreads();
    }
    if (tid == 0) out[loss_off] = 0.25f * s[0] * inv_bnd;
}

// ---------------------------------------------------------------------------
extern "C" void kernel_launch(void* const* d_in, const int* in_sizes, int n_in,
                              void* d_out, int out_size) {
    const float* z    = (const float*)d_in[0];
    const void*  mask = d_in[1];
    const float* cb   = (const float*)d_in[2];
    float* out = (float*)d_out;

    long long BND = in_sizes[0];     // 16777216
    int T = in_sizes[1];             // 65536

    static int attr_set = 0;
    cudaFuncSetAttribute(vq_mma_kernel, cudaFuncAttributeMaxDynamicSharedMemorySize, SMEM_TOTAL);
    (void)attr_set;

    int mask_words = (T / 4 < 1024) ? (T / 4) : 1024;
    prep_kernel<<<1, 512>>>(cb, mask, mask_words);
    convert_cb_kernel<<<128, 256>>>(cb);

    int write_idx  = ((long long)out_size >= BND + T) ? 1 : 0;
    int write_loss = ((long long)out_size >= BND + T + 1) ? 1 : 0;

    vq_mma_kernel<<<NTILES, 256, SMEM_TOTAL>>>(z, mask, cb, out, T, write_idx, write_loss);

    if (write_loss)
        loss_kernel<<<1, 256>>>(out, BND + T, NTILES, 1.0f / (float)BND);
}